// round 2
// baseline (speedup 1.0000x reference)
#include <cuda_runtime.h>
#include <math.h>
#include <stdint.h>

#define NB 4
#define NS 2048
#define ND 1024
#define NH 16
#define NHD 64
#define NTOK (NB*NS)

// Scratch (device globals: allocation-free)
__device__ float g_Q[(size_t)NB*NH*NS*NHD];
__device__ float g_K[(size_t)NB*NH*NS*NHD];
__device__ float g_V[(size_t)NB*NH*NS*NHD];
__device__ float g_AO[(size_t)NTOK*ND];

__device__ __forceinline__ float tf32r(float x){
    uint32_t y;
    asm("cvt.rna.tf32.f32 %0, %1;" : "=r"(y) : "f"(x));
    return __uint_as_float(y);
}

__device__ __forceinline__ void mma8(float c[4], const float a[4], const float b[2]){
    asm volatile(
      "mma.sync.aligned.m16n8k8.row.col.f32.tf32.tf32.f32 "
      "{%0,%1,%2,%3}, {%4,%5,%6,%7}, {%8,%9}, {%0,%1,%2,%3};\n"
      : "+f"(c[0]),"+f"(c[1]),"+f"(c[2]),"+f"(c[3])
      : "r"(__float_as_uint(a[0])),"r"(__float_as_uint(a[1])),
        "r"(__float_as_uint(a[2])),"r"(__float_as_uint(a[3])),
        "r"(__float_as_uint(b[0])),"r"(__float_as_uint(b[1])));
}

// ---------------------------------------------------------------------------
// Kernel 1: QKV projection (tf32x2 split for q/k, plain tf32 for v)
// + fused RMS-norm + 2D RoPE. One block = 64 tokens x one head of one of q/k/v.
// ---------------------------------------------------------------------------
__global__ __launch_bounds__(128) void qkv_kernel(
    const float* __restrict__ X,
    const float* __restrict__ wq, const float* __restrict__ wk, const float* __restrict__ wv,
    const float* __restrict__ cosp, const float* __restrict__ sinp,
    const float* __restrict__ qsc, const float* __restrict__ ksc)
{
    __shared__ float sm[4*64*36];
    float (*Ah)[36] = (float(*)[36])sm;
    float (*Al)[36] = (float(*)[36])(sm + 64*36);
    float (*Bh)[36] = (float(*)[36])(sm + 2*64*36);
    float (*Bl)[36] = (float(*)[36])(sm + 3*64*36);

    const int tid = threadIdx.x;
    const int lane = tid & 31, warp = tid >> 5;
    const int wm = warp >> 1, wn = warp & 1;
    const int lg = lane >> 2, tg = lane & 3;

    const int tok0 = blockIdx.x * 64;
    const int which = blockIdx.y >> 4, head = blockIdx.y & 15;
    const bool split = (which != 2);
    const float* W = (which==0) ? wq : (which==1) ? wk : wv;
    const float* Wb = W + (size_t)head * 64 * ND;
    const float* Xb = X + (size_t)tok0 * ND;

    float c[2][4][4];
    #pragma unroll
    for (int mi=0;mi<2;mi++)
      #pragma unroll
      for (int ni=0;ni<4;ni++)
        #pragma unroll
        for (int q=0;q<4;q++) c[mi][ni][q]=0.f;

    for (int kt = 0; kt < ND/32; ++kt){
        const int k0 = kt * 32;
        __syncthreads();
        #pragma unroll
        for (int i=0;i<4;i++){
            int idx = tid + i*128;
            int row = idx >> 3, c4 = idx & 7;
            float4 va = *(const float4*)(Xb + (size_t)row*ND + k0 + c4*4);
            float4 vb = *(const float4*)(Wb + (size_t)row*ND + k0 + c4*4);
            float ax[4] = {va.x,va.y,va.z,va.w};
            float bx[4] = {vb.x,vb.y,vb.z,vb.w};
            #pragma unroll
            for (int j=0;j<4;j++){
                float ah = tf32r(ax[j]); Ah[row][c4*4+j] = ah;
                float bh = tf32r(bx[j]); Bh[row][c4*4+j] = bh;
                if (split){
                    Al[row][c4*4+j] = tf32r(ax[j]-ah);
                    Bl[row][c4*4+j] = tf32r(bx[j]-bh);
                }
            }
        }
        __syncthreads();
        #pragma unroll
        for (int ks=0;ks<4;ks++){
            const int kk = ks*8;
            float ah[2][4], bh[4][2];
            #pragma unroll
            for (int mi=0;mi<2;mi++){
                int rb = wm*32 + mi*16;
                ah[mi][0]=Ah[rb+lg][kk+tg];   ah[mi][1]=Ah[rb+8+lg][kk+tg];
                ah[mi][2]=Ah[rb+lg][kk+4+tg]; ah[mi][3]=Ah[rb+8+lg][kk+4+tg];
            }
            #pragma unroll
            for (int ni=0;ni<4;ni++){
                int n2 = wn*32 + ni*8;
                bh[ni][0]=Bh[n2+lg][kk+tg]; bh[ni][1]=Bh[n2+lg][kk+4+tg];
            }
            #pragma unroll
            for (int mi=0;mi<2;mi++)
              #pragma unroll
              for (int ni=0;ni<4;ni++)
                mma8(c[mi][ni], ah[mi], bh[ni]);
            if (split){
                float al[2][4], bl[4][2];
                #pragma unroll
                for (int mi=0;mi<2;mi++){
                    int rb = wm*32 + mi*16;
                    al[mi][0]=Al[rb+lg][kk+tg];   al[mi][1]=Al[rb+8+lg][kk+tg];
                    al[mi][2]=Al[rb+lg][kk+4+tg]; al[mi][3]=Al[rb+8+lg][kk+4+tg];
                }
                #pragma unroll
                for (int ni=0;ni<4;ni++){
                    int n2 = wn*32 + ni*8;
                    bl[ni][0]=Bl[n2+lg][kk+tg]; bl[ni][1]=Bl[n2+lg][kk+4+tg];
                }
                #pragma unroll
                for (int mi=0;mi<2;mi++)
                  #pragma unroll
                  for (int ni=0;ni<4;ni++){
                    mma8(c[mi][ni], ah[mi], bl[ni]);
                    mma8(c[mi][ni], al[mi], bh[ni]);
                  }
            }
        }
    }
    __syncthreads();
    // Stage tile for row-wise epilogue (overlay smem)
    float (*Ct)[65] = (float(*)[65])sm;
    #pragma unroll
    for (int mi=0;mi<2;mi++)
      #pragma unroll
      for (int ni=0;ni<4;ni++){
        int row = wm*32+mi*16+lg;
        int col = wn*32+ni*8+2*tg;
        Ct[row][col]     = c[mi][ni][0];
        Ct[row][col+1]   = c[mi][ni][1];
        Ct[row+8][col]   = c[mi][ni][2];
        Ct[row+8][col+1] = c[mi][ni][3];
      }
    __syncthreads();
    if (tid < 64){
        int r = tid;
        int token = tok0 + r;
        int bb = token >> 11, s = token & (NS-1);
        float ssum = 0.f;
        #pragma unroll
        for (int d=0; d<64; d++){ float x = Ct[r][d]; ssum += x*x; }
        float rms = rsqrtf(ssum * (1.f/64.f) + 1e-6f);
        float* op = ((which==0)? g_Q : (which==1)? g_K : g_V)
                    + ((size_t)((bb*NH + head)*NS + s))*NHD;
        if (which == 2){
            #pragma unroll 8
            for (int d=0; d<64; d++) op[d] = Ct[r][d]*rms;
        } else {
            const float* sc = (which==0)? qsc : ksc;
            const float* cb = cosp + (size_t)token*NHD;
            const float* sb = sinp + (size_t)token*NHD;
            #pragma unroll 8
            for (int d=0; d<64; d++){
                int j = d & 31;
                float x  = Ct[r][d]*rms*sc[d];
                int pd = (j<16)? d+16 : d-16;
                float xp = Ct[r][pd]*rms*sc[pd];
                float rot = (j<16)? -xp : xp;
                op[d] = x*cb[d] + rot*sb[d];
            }
        }
    }
}

// ---------------------------------------------------------------------------
// Kernel 2: flash attention. Block = 64 q rows of one (b,h). 4 warps x 16 rows.
// QK^T via tf32x2 (3 mma), online softmax fp32, P*V plain tf32. No scale
// factor (reference has none).
// ---------------------------------------------------------------------------
#define ATTN_SMEM (4*64*68*4)

__global__ __launch_bounds__(128) void attn_kernel()
{
    extern __shared__ float dsm[];
    float (*Kh)[68] = (float(*)[68])dsm;
    float (*Kl)[68] = (float(*)[68])(dsm + 64*68);
    float (*Vs)[68] = (float(*)[68])(dsm + 2*64*68);
    float (*Ps)[68] = (float(*)[68])(dsm + 3*64*68);

    const int tid = threadIdx.x, lane = tid&31, w = tid>>5;
    const int lg = lane>>2, tg = lane&3;
    const int qt = blockIdx.x, h = blockIdx.y, b = blockIdx.z;
    const size_t hb = ((size_t)(b*NH + h))*NS*NHD;

    // stage Q tile (raw fp32) into Kh, then build hi/lo A-fragments
    {
        const float* Qp = g_Q + hb + (size_t)qt*64*NHD;
        #pragma unroll
        for (int i=0;i<8;i++){
            int idx = tid + i*128, row = idx>>4, c4 = idx&15;
            float4 v = *(const float4*)(Qp + (size_t)row*64 + c4*4);
            Kh[row][c4*4+0]=v.x; Kh[row][c4*4+1]=v.y;
            Kh[row][c4*4+2]=v.z; Kh[row][c4*4+3]=v.w;
        }
    }
    __syncthreads();
    float qh[8][4], ql[8][4];
    #pragma unroll
    for (int ks=0;ks<8;ks++){
        int rb = w*16;
        float x0 = Kh[rb+lg][ks*8+tg],   x1 = Kh[rb+8+lg][ks*8+tg];
        float x2 = Kh[rb+lg][ks*8+4+tg], x3 = Kh[rb+8+lg][ks*8+4+tg];
        qh[ks][0]=tf32r(x0); ql[ks][0]=tf32r(x0-qh[ks][0]);
        qh[ks][1]=tf32r(x1); ql[ks][1]=tf32r(x1-qh[ks][1]);
        qh[ks][2]=tf32r(x2); ql[ks][2]=tf32r(x2-qh[ks][2]);
        qh[ks][3]=tf32r(x3); ql[ks][3]=tf32r(x3-qh[ks][3]);
    }
    __syncthreads();

    float ofr[8][4];
    #pragma unroll
    for (int ni=0;ni<8;ni++){ ofr[ni][0]=0;ofr[ni][1]=0;ofr[ni][2]=0;ofr[ni][3]=0; }
    float m0=-INFINITY, m1=-INFINITY, l0=0.f, l1=0.f;

    for (int kt=0; kt<NS/64; ++kt){
        const float* Kp = g_K + hb + (size_t)kt*64*NHD;
        const float* Vp = g_V + hb + (size_t)kt*64*NHD;
        #pragma unroll
        for (int i=0;i<8;i++){
            int idx = tid + i*128, row = idx>>4, c4 = idx&15;
            float4 kv = *(const float4*)(Kp + (size_t)row*64 + c4*4);
            float kx[4]={kv.x,kv.y,kv.z,kv.w};
            #pragma unroll
            for (int j=0;j<4;j++){
                float hh = tf32r(kx[j]);
                Kh[row][c4*4+j]=hh;
                Kl[row][c4*4+j]=tf32r(kx[j]-hh);
            }
            float4 vv = *(const float4*)(Vp + (size_t)row*64 + c4*4);
            Vs[row][c4*4+0]=tf32r(vv.x); Vs[row][c4*4+1]=tf32r(vv.y);
            Vs[row][c4*4+2]=tf32r(vv.z); Vs[row][c4*4+3]=tf32r(vv.w);
        }
        __syncthreads();

        float sfr[8][4];
        #pragma unroll
        for (int ni=0;ni<8;ni++){ sfr[ni][0]=0;sfr[ni][1]=0;sfr[ni][2]=0;sfr[ni][3]=0; }
        #pragma unroll
        for (int ni=0;ni<8;ni++){
            #pragma unroll
            for (int ks=0;ks<8;ks++){
                float bh[2], bl[2];
                bh[0]=Kh[ni*8+lg][ks*8+tg]; bh[1]=Kh[ni*8+lg][ks*8+4+tg];
                bl[0]=Kl[ni*8+lg][ks*8+tg]; bl[1]=Kl[ni*8+lg][ks*8+4+tg];
                mma8(sfr[ni], qh[ks], bh);
                mma8(sfr[ni], qh[ks], bl);
                mma8(sfr[ni], ql[ks], bh);
            }
        }
        // ---- online softmax (rows lg and lg+8 of this warp's 16) ----
        float t0=-INFINITY, t1=-INFINITY;
        #pragma unroll
        for (int ni=0;ni<8;ni++){
            t0 = fmaxf(t0, fmaxf(sfr[ni][0], sfr[ni][1]));
            t1 = fmaxf(t1, fmaxf(sfr[ni][2], sfr[ni][3]));
        }
        t0 = fmaxf(t0, __shfl_xor_sync(0xffffffffu, t0, 1));
        t0 = fmaxf(t0, __shfl_xor_sync(0xffffffffu, t0, 2));
        t1 = fmaxf(t1, __shfl_xor_sync(0xffffffffu, t1, 1));
        t1 = fmaxf(t1, __shfl_xor_sync(0xffffffffu, t1, 2));
        float mn0 = fmaxf(m0, t0), mn1 = fmaxf(m1, t1);
        float a0 = __expf(m0 - mn0), a1 = __expf(m1 - mn1);
        float p0 = 0.f, p1 = 0.f;
        #pragma unroll
        for (int ni=0;ni<8;ni++){
            sfr[ni][0] = __expf(sfr[ni][0]-mn0); p0 += sfr[ni][0];
            sfr[ni][1] = __expf(sfr[ni][1]-mn0); p0 += sfr[ni][1];
            sfr[ni][2] = __expf(sfr[ni][2]-mn1); p1 += sfr[ni][2];
            sfr[ni][3] = __expf(sfr[ni][3]-mn1); p1 += sfr[ni][3];
        }
        p0 += __shfl_xor_sync(0xffffffffu, p0, 1);
        p0 += __shfl_xor_sync(0xffffffffu, p0, 2);
        p1 += __shfl_xor_sync(0xffffffffu, p1, 1);
        p1 += __shfl_xor_sync(0xffffffffu, p1, 2);
        l0 = l0*a0 + p0; l1 = l1*a1 + p1;
        m0 = mn0; m1 = mn1;
        #pragma unroll
        for (int ni=0;ni<8;ni++){
            ofr[ni][0]*=a0; ofr[ni][1]*=a0; ofr[ni][2]*=a1; ofr[ni][3]*=a1;
            int col = ni*8 + 2*tg;
            Ps[w*16+lg][col]     = tf32r(sfr[ni][0]);
            Ps[w*16+lg][col+1]   = tf32r(sfr[ni][1]);
            Ps[w*16+8+lg][col]   = tf32r(sfr[ni][2]);
            Ps[w*16+8+lg][col+1] = tf32r(sfr[ni][3]);
        }
        __syncwarp();
        // ---- O += P * V ----
        #pragma unroll
        for (int k2=0;k2<8;k2++){
            float pa[4];
            pa[0]=Ps[w*16+lg][k2*8+tg];
            pa[1]=Ps[w*16+8+lg][k2*8+tg];
            pa[2]=Ps[w*16+lg][k2*8+4+tg];
            pa[3]=Ps[w*16+8+lg][k2*8+4+tg];
            #pragma unroll
            for (int ni=0;ni<8;ni++){
                float bv[2];
                bv[0]=Vs[k2*8+tg][ni*8+lg];
                bv[1]=Vs[k2*8+4+tg][ni*8+lg];
                mma8(ofr[ni], pa, bv);
            }
        }
        __syncthreads();
    }
    float i0 = 1.f/l0, i1 = 1.f/l1;
    int r0 = qt*64 + w*16 + lg;
    float* o0 = g_AO + ((size_t)b*NS + r0)*ND + h*64;
    float* o1 = o0 + (size_t)8*ND;
    #pragma unroll
    for (int ni=0;ni<8;ni++){
        int col = ni*8 + 2*tg;
        o0[col]   = ofr[ni][0]*i0;
        o0[col+1] = ofr[ni][1]*i0;
        o1[col]   = ofr[ni][2]*i1;
        o1[col+1] = ofr[ni][3]*i1;
    }
}

// ---------------------------------------------------------------------------
// Kernel 3: output projection out = AO @ wo^T (plain tf32)
// ---------------------------------------------------------------------------
__global__ __launch_bounds__(128) void oproj_kernel(
    const float* __restrict__ wo, float* __restrict__ out)
{
    __shared__ float sm[2*64*36];
    float (*Ah)[36] = (float(*)[36])sm;
    float (*Bh)[36] = (float(*)[36])(sm + 64*36);

    const int tid = threadIdx.x;
    const int lane = tid & 31, warp = tid >> 5;
    const int wm = warp >> 1, wn = warp & 1;
    const int lg = lane >> 2, tg = lane & 3;

    const int tok0 = blockIdx.x * 64;
    const int n0 = blockIdx.y * 64;
    const float* Xb = g_AO + (size_t)tok0 * ND;
    const float* Wb = wo + (size_t)n0 * ND;

    float c[2][4][4];
    #pragma unroll
    for (int mi=0;mi<2;mi++)
      #pragma unroll
      for (int ni=0;ni<4;ni++)
        #pragma unroll
        for (int q=0;q<4;q++) c[mi][ni][q]=0.f;

    for (int kt = 0; kt < ND/32; ++kt){
        const int k0 = kt * 32;
        __syncthreads();
        #pragma unroll
        for (int i=0;i<4;i++){
            int idx = tid + i*128;
            int row = idx >> 3, c4 = idx & 7;
            float4 va = *(const float4*)(Xb + (size_t)row*ND + k0 + c4*4);
            float4 vb = *(const float4*)(Wb + (size_t)row*ND + k0 + c4*4);
            Ah[row][c4*4+0]=tf32r(va.x); Ah[row][c4*4+1]=tf32r(va.y);
            Ah[row][c4*4+2]=tf32r(va.z); Ah[row][c4*4+3]=tf32r(va.w);
            Bh[row][c4*4+0]=tf32r(vb.x); Bh[row][c4*4+1]=tf32r(vb.y);
            Bh[row][c4*4+2]=tf32r(vb.z); Bh[row][c4*4+3]=tf32r(vb.w);
        }
        __syncthreads();
        #pragma unroll
        for (int ks=0;ks<4;ks++){
            const int kk = ks*8;
            float a[2][4], bfr[4][2];
            #pragma unroll
            for (int mi=0;mi<2;mi++){
                int rb = wm*32 + mi*16;
                a[mi][0]=Ah[rb+lg][kk+tg];   a[mi][1]=Ah[rb+8+lg][kk+tg];
                a[mi][2]=Ah[rb+lg][kk+4+tg]; a[mi][3]=Ah[rb+8+lg][kk+4+tg];
            }
            #pragma unroll
            for (int ni=0;ni<4;ni++){
                int n2 = wn*32 + ni*8;
                bfr[ni][0]=Bh[n2+lg][kk+tg]; bfr[ni][1]=Bh[n2+lg][kk+4+tg];
            }
            #pragma unroll
            for (int mi=0;mi<2;mi++)
              #pragma unroll
              for (int ni=0;ni<4;ni++)
                mma8(c[mi][ni], a[mi], bfr[ni]);
        }
    }
    #pragma unroll
    for (int mi=0;mi<2;mi++)
      #pragma unroll
      for (int ni=0;ni<4;ni++){
        int row = tok0 + wm*32 + mi*16 + lg;
        int col = n0 + wn*32 + ni*8 + 2*tg;
        float* p0 = out + (size_t)row*ND + col;
        float* p1 = out + (size_t)(row+8)*ND + col;
        p0[0] = c[mi][ni][0]; p0[1] = c[mi][ni][1];
        p1[0] = c[mi][ni][2]; p1[1] = c[mi][ni][3];
      }
}

// ---------------------------------------------------------------------------
extern "C" void kernel_launch(void* const* d_in, const int* in_sizes, int n_in,
                              void* d_out, int out_size)
{
    (void)in_sizes; (void)n_in; (void)out_size;
    const float* X    = (const float*)d_in[0];
    const float* cosp = (const float*)d_in[1];
    const float* sinp = (const float*)d_in[2];
    // d_in[3] = position_ids (unused by reference)
    const float* wq   = (const float*)d_in[4];
    const float* wk   = (const float*)d_in[5];
    const float* wv   = (const float*)d_in[6];
    const float* wo   = (const float*)d_in[7];
    const float* qsc  = (const float*)d_in[8];
    const float* ksc  = (const float*)d_in[9];
    float* out = (float*)d_out;

    cudaFuncSetAttribute(attn_kernel,
                         cudaFuncAttributeMaxDynamicSharedMemorySize, ATTN_SMEM);

    qkv_kernel<<<dim3(NTOK/64, 48), 128>>>(X, wq, wk, wv, cosp, sinp, qsc, ksc);
    attn_kernel<<<dim3(NS/64, NH, NB), 128, ATTN_SMEM>>>();
    oproj_kernel<<<dim3(NTOK/64, ND/64), 128>>>(wo, out);
}